// round 13
// baseline (speedup 1.0000x reference)
#include <cuda_runtime.h>
#include <cuda_bf16.h>
#include <cstdint>

// RNN: B=4096, T=1024, H=64, scalar input, C=5 head.
//   h_{t+1}[b,i] = tanh(x[b,t]*w_ih[i] + b_ih[i] + b_hh[i] + sum_j h_t[b,j]*w_hh[i,j])
//   out[b,c]     = sum_j hT[b,j]*w_head[c,j] + b_head[c]
//
// R12: HMMA bf16-split, NB=16 per CTA, grid=256 => 2 co-resident CTAs/SM
// (4 warps/SMSP from two hardware-independent CTAs). Each warp owns one
// N-tile (M=16 batches x 8 i): 12 MMAs in 3 depth-4 chains, 4 epilogue
// values per lane -- shorter serial tail than R11, overlapped across CTAs.
// Per-CTA hashed skew preamble seeds anti-phase between co-resident CTAs.

#define BB 4096
#define TT 1024
#define HH 64
#define CC 5
#define NB 16
#define NTHREADS 256
#define HSTR 72            // bf16 elems per h row = 144 B (bank shift 4/row)

typedef uint32_t u32;

__device__ __forceinline__ u32 smem_u32(const void* p) {
    u32 a;
    asm("{ .reg .u64 t; cvta.to.shared.u64 t, %1; cvt.u32.u64 %0, t; }"
        : "=r"(a) : "l"(p));
    return a;
}
__device__ __forceinline__ u32 pkbf(float a, float b) {
    __nv_bfloat162 t = __floats2bfloat162_rn(a, b);
    return *reinterpret_cast<u32*>(&t);
}
__device__ __forceinline__ float ftanh(float xv) {
    // tanh(x) = 1 - 2/(e^{2x}+1); exact at saturation via inf.
    float e = __expf(2.0f * xv);
    return 1.0f - __fdividef(2.0f, e + 1.0f);
}
__device__ __forceinline__ void ldm4(u32* r, u32 addr) {
    asm volatile("ldmatrix.sync.aligned.m8n8.x4.shared.b16 {%0,%1,%2,%3}, [%4];"
                 : "=r"(r[0]), "=r"(r[1]), "=r"(r[2]), "=r"(r[3]) : "r"(addr));
}
__device__ __forceinline__ void mma16816(float* d, const u32* a, const u32* b) {
    asm volatile(
        "mma.sync.aligned.m16n8k16.row.col.f32.bf16.bf16.f32 "
        "{%0,%1,%2,%3}, {%4,%5,%6,%7}, {%8,%9}, {%0,%1,%2,%3};"
        : "+f"(d[0]), "+f"(d[1]), "+f"(d[2]), "+f"(d[3])
        : "r"(a[0]), "r"(a[1]), "r"(a[2]), "r"(a[3]), "r"(b[0]), "r"(b[1]));
}

extern "C" __global__ void __launch_bounds__(NTHREADS, 2)
rnn_hmma3_kernel(const float* __restrict__ x,
                 const float* __restrict__ w_ih,
                 const float* __restrict__ b_ih,
                 const float* __restrict__ w_hh,
                 const float* __restrict__ b_hh,
                 const float* __restrict__ w_head,
                 const float* __restrict__ b_head,
                 float* __restrict__ out)
{
    __shared__ __align__(16) __nv_bfloat16 hhi[2][NB][HSTR];  // 4608 B
    __shared__ __align__(16) __nv_bfloat16 hlo[2][NB][HSTR];  // 4608 B
    __shared__ float xs[32][NB];                              // 2048 B
    __shared__ float hsfin[NB][HH];                           // 4096 B

    const int tid  = threadIdx.x;
    const int lane = tid & 31;
    const int wrp  = tid >> 5;          // N-tile: i in [8*wrp, 8*wrp+8)
    const int gb0  = blockIdx.x * NB;
    const int tig  = lane & 3;
    const int gid  = lane >> 2;

    // --- B fragments (W^T), loop-invariant, bf16 hi/lo split ---
    // lane (gid,tig) covers row i = 8*wrp + gid, k = ks*16 + {2tig,2tig+1,+8,+9}
    u32 bhi[4][2], blo[4][2];
    {
        const int i = wrp * 8 + gid;
        const float* wr = w_hh + (size_t)i * HH;
#pragma unroll
        for (int ks = 0; ks < 4; ks++) {
            int j0 = ks * 16 + 2 * tig;
            float w0 = wr[j0],     w1 = wr[j0 + 1];
            float w2 = wr[j0 + 8], w3 = wr[j0 + 9];
            float h0 = __bfloat162float(__float2bfloat16(w0));
            float h1 = __bfloat162float(__float2bfloat16(w1));
            float h2 = __bfloat162float(__float2bfloat16(w2));
            float h3 = __bfloat162float(__float2bfloat16(w3));
            bhi[ks][0] = pkbf(w0, w1);
            bhi[ks][1] = pkbf(w2, w3);
            blo[ks][0] = pkbf(w0 - h0, w1 - h1);
            blo[ks][1] = pkbf(w2 - h2, w3 - h3);
        }
    }

    // --- per-lane epilogue constants: i0 = 8*wrp + 2*tig, i0+1 ---
    const int i0 = wrp * 8 + 2 * tig;
    float wihv[2] = { w_ih[i0], w_ih[i0 + 1] };
    float biasv[2] = { b_ih[i0] + b_hh[i0], b_ih[i0 + 1] + b_hh[i0 + 1] };

    // --- zero h buffer 0 ---
    for (int e = tid; e < NB * HSTR / 2; e += NTHREADS) {
        ((u32*)hhi[0])[e] = 0u;
        ((u32*)hlo[0])[e] = 0u;
    }
    // --- stage x chunk 0: xs[tc][b] ---
    for (int e = tid; e < NB * 32; e += NTHREADS) {
        int b = e >> 5, tcc = e & 31;
        xs[tcc][b] = x[(size_t)(gb0 + b) * TT + tcc];
    }

    const u32 hhi_a = smem_u32(hhi);
    const u32 hlo_a = smem_u32(hlo);
    // A tile = all 16 batches: row (lane&15), halves via lane>>4
    const u32 aoff = (u32)((lane & 15) * 144 + ((lane >> 4) & 1) * 16);

    const int br0 = gid;        // epilogue batches
    const int br1 = gid + 8;

    __syncthreads();

    // --- per-CTA hashed skew: desync co-resident CTAs (0..3 x ~512 cyc) ---
    {
        int links = (int)((blockIdx.x * 2654435761u) >> 30) * 128;
        float z = biasv[0] + 1.0f;
        for (int i = 0; i < links; i++)
            asm volatile("fma.rn.f32 %0, %0, %1, %2;"
                         : "+f"(z) : "f"(0.9999999f), "f"(1e-30f));
        if (z == -123456.75f) xs[0][0] = z;   // defeat DCE, never true
    }

    int cur = 0;
    for (int t = 0; t < TT; t++) {
        const int tc = t & 31;
        if (tc == 0 && t > 0) {
            for (int e = tid; e < NB * 32; e += NTHREADS) {
                int b = e >> 5, tcc = e & 31;
                xs[tcc][b] = x[(size_t)(gb0 + b) * TT + t + tcc];
            }
            __syncthreads();
        }

        const u32 bufo = (u32)cur * (NB * HSTR * 2);

        // 3 independent depth-4 HMMA chains (12 MMAs)
        float dA[4] = {}, dB[4] = {}, dC[4] = {};
#pragma unroll
        for (int ks = 0; ks < 4; ks++) {
            u32 ahi[4], alo[4];
            ldm4(ahi, hhi_a + bufo + aoff + ks * 32);
            ldm4(alo, hlo_a + bufo + aoff + ks * 32);
            mma16816(dA, ahi, bhi[ks]);
            mma16816(dB, alo, bhi[ks]);
            mma16816(dC, ahi, blo[ks]);
        }

        // epilogue: combine, +x*w_ih+bias, tanh, split bf16 hi/lo, store
        const float xv0 = xs[tc][br0];
        const float xv1 = xs[tc][br1];
        const int nxt = cur ^ 1;

        float s0 = dA[0] + dB[0] + dC[0] + fmaf(xv0, wihv[0], biasv[0]);
        float s1 = dA[1] + dB[1] + dC[1] + fmaf(xv0, wihv[1], biasv[1]);
        float s2 = dA[2] + dB[2] + dC[2] + fmaf(xv1, wihv[0], biasv[0]);
        float s3 = dA[3] + dB[3] + dC[3] + fmaf(xv1, wihv[1], biasv[1]);
        float v0 = ftanh(s0), v1 = ftanh(s1), v2 = ftanh(s2), v3 = ftanh(s3);

        *(u32*)&hhi[nxt][br0][i0] = pkbf(v0, v1);
        *(u32*)&hhi[nxt][br1][i0] = pkbf(v2, v3);
        float l0 = v0 - __bfloat162float(__float2bfloat16(v0));
        float l1 = v1 - __bfloat162float(__float2bfloat16(v1));
        float l2 = v2 - __bfloat162float(__float2bfloat16(v2));
        float l3 = v3 - __bfloat162float(__float2bfloat16(v3));
        *(u32*)&hlo[nxt][br0][i0] = pkbf(l0, l1);
        *(u32*)&hlo[nxt][br1][i0] = pkbf(l2, l3);

        if (t == TT - 1) {
            hsfin[br0][i0] = v0; hsfin[br0][i0 + 1] = v1;
            hsfin[br1][i0] = v2; hsfin[br1][i0 + 1] = v3;
        }
        __syncthreads();
        cur ^= 1;
    }

    // --- head: out[b,c] = sum_j hT[b,j]*w_head[c,j] + b_head[c] (fp32) ---
    if (tid < NB * CC) {
        const int b = tid / CC, c = tid % CC;
        const float* hf = hsfin[b];
        float s = b_head[c];
#pragma unroll
        for (int j = 0; j < HH; j++)
            s = fmaf(hf[j], w_head[c * HH + j], s);
        out[(size_t)(gb0 + b) * CC + c] = s;
    }
}

extern "C" void kernel_launch(void* const* d_in, const int* in_sizes, int n_in,
                              void* d_out, int out_size)
{
    (void)in_sizes; (void)n_in; (void)out_size;
    const float* x      = (const float*)d_in[0];
    const float* w_ih   = (const float*)d_in[1];
    const float* b_ih   = (const float*)d_in[2];
    const float* w_hh   = (const float*)d_in[3];
    const float* b_hh   = (const float*)d_in[4];
    const float* w_head = (const float*)d_in[5];
    const float* b_head = (const float*)d_in[6];
    float* out = (float*)d_out;

    rnn_hmma3_kernel<<<BB / NB, NTHREADS>>>(
        x, w_ih, b_ih, w_hh, b_hh, w_head, b_head, out);
}

// round 14
// speedup vs baseline: 1.1885x; 1.1885x over previous
#include <cuda_runtime.h>
#include <cuda_bf16.h>
#include <cstdint>

// RNN: B=4096, T=1024, H=64, scalar input, C=5 head.
//   h_{t+1}[b,i] = tanh(x[b,t]*w_ih[i] + b_ih[i] + b_hh[i] + sum_j h_t[b,j]*w_hh[i,j])
//   out[b,c]     = sum_j hT[b,j]*w_head[c,j] + b_head[c]
//
// R13 = R11 (HMMA bf16-split, decoupled anti-phased batch-halves, 498us)
// with the epilogue tanh switched to the HW instruction tanh.approx.f32.
// MUFU was the hidden throughput binder: 2 MUFU (ex2+rcp) + ~4 FFMA per
// value -> 256 MUFU-cyc/SMSP/step in the serial tail. tanh.approx cuts
// that 4x (1 MUFU/value). Accuracy: ~6e-4 abs per step, measured error
// contraction ~0.17 through T=1024 -> final ~1e-4 < 1e-3 threshold.

#define BB 4096
#define TT 1024
#define HH 64
#define CC 5
#define NB 32
#define NTHREADS 256
#define HSTR 72            // bf16 elems per h row = 144 B
#define SKEW_FMA 160       // dependent FFMA chain for half 1, ~640 cyc

typedef uint32_t u32;

__device__ __forceinline__ u32 smem_u32(const void* p) {
    u32 a;
    asm("{ .reg .u64 t; cvta.to.shared.u64 t, %1; cvt.u32.u64 %0, t; }"
        : "=r"(a) : "l"(p));
    return a;
}
__device__ __forceinline__ u32 pkbf(float a, float b) {
    __nv_bfloat162 t = __floats2bfloat162_rn(a, b);
    return *reinterpret_cast<u32*>(&t);
}
__device__ __forceinline__ float ftanh(float xv) {
    float y;
    asm("tanh.approx.f32 %0, %1;" : "=f"(y) : "f"(xv));
    return y;
}
__device__ __forceinline__ void ldm4(u32* r, u32 addr) {
    asm volatile("ldmatrix.sync.aligned.m8n8.x4.shared.b16 {%0,%1,%2,%3}, [%4];"
                 : "=r"(r[0]), "=r"(r[1]), "=r"(r[2]), "=r"(r[3]) : "r"(addr));
}
__device__ __forceinline__ void mma16816(float* d, const u32* a, const u32* b) {
    asm volatile(
        "mma.sync.aligned.m16n8k16.row.col.f32.bf16.bf16.f32 "
        "{%0,%1,%2,%3}, {%4,%5,%6,%7}, {%8,%9}, {%0,%1,%2,%3};"
        : "+f"(d[0]), "+f"(d[1]), "+f"(d[2]), "+f"(d[3])
        : "r"(a[0]), "r"(a[1]), "r"(a[2]), "r"(a[3]), "r"(b[0]), "r"(b[1]));
}
__device__ __forceinline__ void bar_half(int mt) {
    asm volatile("bar.sync %0, 128;" :: "r"(1 + mt) : "memory");
}

extern "C" __global__ void __launch_bounds__(NTHREADS, 1)
rnn_hmma4_kernel(const float* __restrict__ x,
                 const float* __restrict__ w_ih,
                 const float* __restrict__ b_ih,
                 const float* __restrict__ w_hh,
                 const float* __restrict__ b_hh,
                 const float* __restrict__ w_head,
                 const float* __restrict__ b_head,
                 float* __restrict__ out)
{
    __shared__ __align__(16) __nv_bfloat16 hhi[2][NB][HSTR];  // 9216 B
    __shared__ __align__(16) __nv_bfloat16 hlo[2][NB][HSTR];  // 9216 B
    __shared__ float xs[32][NB];                              // 4096 B
    __shared__ float hsfin[NB][HH];                           // 8192 B

    const int tid  = threadIdx.x;
    const int lane = tid & 31;
    const int wrp  = tid >> 5;
    const int nt2  = wrp & 3;           // N-tile pair: i in [nt2*16, nt2*16+16)
    const int mt   = wrp >> 2;          // batch half: batches [mt*16, mt*16+16)
    const int gb0  = blockIdx.x * NB;
    const int tig  = lane & 3;          // thread-in-group
    const int gid  = lane >> 2;         // group id
    const int ht   = tid & 127;         // thread id within half

    // --- B fragments (W^T), loop-invariant, bf16 hi/lo split ---
    u32 bhi[2][4][2], blo[2][4][2];
#pragma unroll
    for (int nt = 0; nt < 2; nt++) {
        const int i = nt2 * 16 + nt * 8 + gid;
        const float* wr = w_hh + (size_t)i * HH;
#pragma unroll
        for (int ks = 0; ks < 4; ks++) {
            int j0 = ks * 16 + 2 * tig;
            float w0 = wr[j0],     w1 = wr[j0 + 1];
            float w2 = wr[j0 + 8], w3 = wr[j0 + 9];
            float h0 = __bfloat162float(__float2bfloat16(w0));
            float h1 = __bfloat162float(__float2bfloat16(w1));
            float h2 = __bfloat162float(__float2bfloat16(w2));
            float h3 = __bfloat162float(__float2bfloat16(w3));
            bhi[nt][ks][0] = pkbf(w0, w1);
            bhi[nt][ks][1] = pkbf(w2, w3);
            blo[nt][ks][0] = pkbf(w0 - h0, w1 - h1);
            blo[nt][ks][1] = pkbf(w2 - h2, w3 - h3);
        }
    }

    // --- per-lane epilogue constants ---
    float wihv[2][2], biasv[2][2];
#pragma unroll
    for (int nt = 0; nt < 2; nt++)
#pragma unroll
        for (int c = 0; c < 2; c++) {
            int i = nt2 * 16 + nt * 8 + 2 * tig + c;
            wihv[nt][c]  = w_ih[i];
            biasv[nt][c] = b_ih[i] + b_hh[i];
        }

    // --- zero h buffer 0 ---
    for (int e = tid; e < NB * HSTR / 2; e += NTHREADS) {
        ((u32*)hhi[0])[e] = 0u;
        ((u32*)hlo[0])[e] = 0u;
    }
    // --- stage x chunk 0 (per half) ---
    for (int e = ht; e < 16 * 32; e += 128) {
        int b = mt * 16 + (e >> 5), tcc = e & 31;
        xs[tcc][b] = x[(size_t)(gb0 + b) * TT + tcc];
    }

    const u32 hhi_a = smem_u32(hhi);
    const u32 hlo_a = smem_u32(hlo);
    const u32 aoff  = (u32)((mt * 16 + (lane & 15)) * 144 + ((lane >> 4) & 1) * 16);

    const int br0 = mt * 16 + gid;
    const int br1 = br0 + 8;

    __syncthreads();     // covers cross-half zero/stage init

    // --- anti-phase skew: half 1 burns ~640 cyc once (latency-bound chain) ---
    if (mt == 1) {
        float z = biasv[0][0] + 1.0f;
#pragma unroll
        for (int i = 0; i < SKEW_FMA; i++)
            asm volatile("fma.rn.f32 %0, %0, %1, %2;"
                         : "+f"(z) : "f"(0.9999999f), "f"(1e-30f));
        if (z == -123456.75f) xs[0][0] = z;   // defeat DCE, never true
    }

    int cur = 0;
    for (int t = 0; t < TT; t++) {
        const int tc = t & 31;
        if (tc == 0 && t > 0) {
            for (int e = ht; e < 16 * 32; e += 128) {
                int b = mt * 16 + (e >> 5), tcc = e & 31;
                xs[tcc][b] = x[(size_t)(gb0 + b) * TT + t + tcc];
            }
            bar_half(mt);
        }

        const u32 bufo = (u32)cur * (NB * HSTR * 2);

        // 6 independent depth-4 HMMA chains
        float dA[2][4] = {}, dB[2][4] = {}, dC[2][4] = {};
#pragma unroll
        for (int ks = 0; ks < 4; ks++) {
            u32 ahi[4], alo[4];
            ldm4(ahi, hhi_a + bufo + aoff + ks * 32);
            ldm4(alo, hlo_a + bufo + aoff + ks * 32);
            mma16816(dA[0], ahi, bhi[0][ks]);
            mma16816(dA[1], ahi, bhi[1][ks]);
            mma16816(dB[0], alo, bhi[0][ks]);
            mma16816(dB[1], alo, bhi[1][ks]);
            mma16816(dC[0], ahi, blo[0][ks]);
            mma16816(dC[1], ahi, blo[1][ks]);
        }

        // epilogue: combine, +x*w_ih+bias, HW tanh, split bf16 hi/lo, store
        const float xv0 = xs[tc][br0];
        const float xv1 = xs[tc][br1];
        const int nxt = cur ^ 1;
#pragma unroll
        for (int nt = 0; nt < 2; nt++) {
            const int ic = nt2 * 16 + nt * 8 + 2 * tig;
            float s0 = (dA[nt][0] + dB[nt][0]) + (dC[nt][0] + fmaf(xv0, wihv[nt][0], biasv[nt][0]));
            float s1 = (dA[nt][1] + dB[nt][1]) + (dC[nt][1] + fmaf(xv0, wihv[nt][1], biasv[nt][1]));
            float s2 = (dA[nt][2] + dB[nt][2]) + (dC[nt][2] + fmaf(xv1, wihv[nt][0], biasv[nt][0]));
            float s3 = (dA[nt][3] + dB[nt][3]) + (dC[nt][3] + fmaf(xv1, wihv[nt][1], biasv[nt][1]));
            float v0 = ftanh(s0), v1 = ftanh(s1), v2 = ftanh(s2), v3 = ftanh(s3);
            *(u32*)&hhi[nxt][br0][ic] = pkbf(v0, v1);
            *(u32*)&hhi[nxt][br1][ic] = pkbf(v2, v3);
            float l0 = v0 - __bfloat162float(__float2bfloat16(v0));
            float l1 = v1 - __bfloat162float(__float2bfloat16(v1));
            float l2 = v2 - __bfloat162float(__float2bfloat16(v2));
            float l3 = v3 - __bfloat162float(__float2bfloat16(v3));
            *(u32*)&hlo[nxt][br0][ic] = pkbf(l0, l1);
            *(u32*)&hlo[nxt][br1][ic] = pkbf(l2, l3);
            if (t == TT - 1) {
                hsfin[br0][ic] = v0; hsfin[br0][ic + 1] = v1;
                hsfin[br1][ic] = v2; hsfin[br1][ic + 1] = v3;
            }
        }
        bar_half(mt);
        cur ^= 1;
    }

    __syncthreads();     // re-align halves before the head

    // --- head: out[b,c] = sum_j hT[b,j]*w_head[c,j] + b_head[c] (fp32) ---
    if (tid < NB * CC) {
        const int b = tid / CC, c = tid % CC;
        const float* hf = hsfin[b];
        float s = b_head[c];
#pragma unroll
        for (int j = 0; j < HH; j++)
            s = fmaf(hf[j], w_head[c * HH + j], s);
        out[(size_t)(gb0 + b) * CC + c] = s;
    }
}

extern "C" void kernel_launch(void* const* d_in, const int* in_sizes, int n_in,
                              void* d_out, int out_size)
{
    (void)in_sizes; (void)n_in; (void)out_size;
    const float* x      = (const float*)d_in[0];
    const float* w_ih   = (const float*)d_in[1];
    const float* b_ih   = (const float*)d_in[2];
    const float* w_hh   = (const float*)d_in[3];
    const float* b_hh   = (const float*)d_in[4];
    const float* w_head = (const float*)d_in[5];
    const float* b_head = (const float*)d_in[6];
    float* out = (float*)d_out;

    rnn_hmma4_kernel<<<BB / NB, NTHREADS>>>(
        x, w_ih, b_ih, w_hh, b_hh, w_head, b_head, out);
}

// round 15
// speedup vs baseline: 1.4535x; 1.2229x over previous
#include <cuda_runtime.h>
#include <cuda_bf16.h>
#include <cstdint>

// RNN: B=4096, T=1024, H=64, scalar input, C=5 head.
//   h_{t+1}[b,i] = tanh(x[b,t]*w_ih[i] + b_ih[i] + b_hh[i] + sum_j h_t[b,j]*w_hh[i,j])
//   out[b,c]     = sum_j hT[b,j]*w_head[c,j] + b_head[c]
//
// R14: operand swap. A = W (M side, 16-i tiles, LOOP-INVARIANT register
// fragments), B = H (N side, n8 -> 8-batch groups). 512 threads / 16 warps:
// warp (ir = wrp&3, bc = wrp>>2) computes D[16i x 8b] with full j-sum (no
// partials). 4 independent batch-groups x 4 warps, named 128-thread
// barriers, 4-phase skew; each SMSP hosts one warp of each group.
// h stored transposed hT[i][b] (16B rows): B-frags via ldmatrix.x2.trans,
// stores as packed STS.32. bf16-split (3 products) + HW tanh.approx.

#define BB 4096
#define TT 1024
#define HH 64
#define CC 5
#define NB 32
#define NTHREADS 512

typedef uint32_t u32;

__device__ __forceinline__ u32 smem_u32(const void* p) {
    u32 a;
    asm("{ .reg .u64 t; cvta.to.shared.u64 t, %1; cvt.u32.u64 %0, t; }"
        : "=r"(a) : "l"(p));
    return a;
}
__device__ __forceinline__ u32 pkbf(float a, float b) {
    __nv_bfloat162 t = __floats2bfloat162_rn(a, b);
    return *reinterpret_cast<u32*>(&t);
}
__device__ __forceinline__ float ftanh(float xv) {
    float y;
    asm("tanh.approx.f32 %0, %1;" : "=f"(y) : "f"(xv));
    return y;
}
__device__ __forceinline__ void ldm2t(u32* r, u32 addr) {
    asm volatile("ldmatrix.sync.aligned.m8n8.x2.trans.shared.b16 {%0,%1}, [%2];"
                 : "=r"(r[0]), "=r"(r[1]) : "r"(addr));
}
__device__ __forceinline__ void mma16816(float* d, const u32* a, const u32* b) {
    asm volatile(
        "mma.sync.aligned.m16n8k16.row.col.f32.bf16.bf16.f32 "
        "{%0,%1,%2,%3}, {%4,%5,%6,%7}, {%8,%9}, {%0,%1,%2,%3};"
        : "+f"(d[0]), "+f"(d[1]), "+f"(d[2]), "+f"(d[3])
        : "r"(a[0]), "r"(a[1]), "r"(a[2]), "r"(a[3]), "r"(b[0]), "r"(b[1]));
}
__device__ __forceinline__ void bar_grp(int id) {
    asm volatile("bar.sync %0, 128;" :: "r"(1 + id) : "memory");
}

extern "C" __global__ void __launch_bounds__(NTHREADS, 1)
rnn_swap_kernel(const float* __restrict__ x,
                const float* __restrict__ w_ih,
                const float* __restrict__ b_ih,
                const float* __restrict__ w_hh,
                const float* __restrict__ b_hh,
                const float* __restrict__ w_head,
                const float* __restrict__ b_head,
                float* __restrict__ out)
{
    // hT[buf][group][hi/lo][i(64) * b(8)] bf16, 16B rows -> 16 KB total
    __shared__ __align__(16) __nv_bfloat16 hT[2][4][2][HH * 8];
    __shared__ float xs[4][32][8];            // 4 KB  [group][tc][b]
    __shared__ float hsfin[NB][HH];           // 8 KB

    const int tid  = threadIdx.x;
    const int lane = tid & 31;
    const int wrp  = tid >> 5;
    const int bc   = wrp >> 2;          // batch group 0..3 (8 batches)
    const int ir   = wrp & 3;           // i-tile 0..3 (16 i's)
    const int tig  = lane & 3;
    const int gid  = lane >> 2;
    const int ht   = tid & 127;         // thread id within group
    const int gb0  = blockIdx.x * NB;
    const int gbg  = gb0 + bc * 8;      // group's global batch base

    // --- A fragments: W rows (loop-invariant), bf16 hi/lo split ---
    // lane (gid,tig): rows ig, ig+8; k = slab*16 + {2tig,2tig+1, +8,+9}
    const int ig = ir * 16 + gid;
    u32 ahi[4][4], alo[4][4];
#pragma unroll
    for (int s = 0; s < 4; s++) {
        const float* w0 = w_hh + (size_t)ig * HH + s * 16;
        const float* w1 = w_hh + (size_t)(ig + 8) * HH + s * 16;
        float e00 = w0[2*tig],     e01 = w0[2*tig + 1];
        float e10 = w1[2*tig],     e11 = w1[2*tig + 1];
        float e02 = w0[2*tig + 8], e03 = w0[2*tig + 9];
        float e12 = w1[2*tig + 8], e13 = w1[2*tig + 9];
        ahi[s][0] = pkbf(e00, e01);
        ahi[s][1] = pkbf(e10, e11);
        ahi[s][2] = pkbf(e02, e03);
        ahi[s][3] = pkbf(e12, e13);
        alo[s][0] = pkbf(e00 - __bfloat162float(__float2bfloat16(e00)),
                         e01 - __bfloat162float(__float2bfloat16(e01)));
        alo[s][1] = pkbf(e10 - __bfloat162float(__float2bfloat16(e10)),
                         e11 - __bfloat162float(__float2bfloat16(e11)));
        alo[s][2] = pkbf(e02 - __bfloat162float(__float2bfloat16(e02)),
                         e03 - __bfloat162float(__float2bfloat16(e03)));
        alo[s][3] = pkbf(e12 - __bfloat162float(__float2bfloat16(e12)),
                         e13 - __bfloat162float(__float2bfloat16(e13)));
    }

    // --- epilogue constants: this lane's two i rows ---
    const float wihv0 = w_ih[ig],     wihv1 = w_ih[ig + 8];
    const float biav0 = b_ih[ig] + b_hh[ig];
    const float biav1 = b_ih[ig + 8] + b_hh[ig + 8];

    // --- zero h buffer 0 ---
    for (int e = tid; e < 4 * 2 * HH * 8 / 2; e += NTHREADS)
        ((u32*)hT[0])[e] = 0u;

    // --- stage x chunk 0 (per group, coalesced along t) ---
    for (int e = ht; e < 8 * 32; e += 128) {
        int b = e >> 5, tcc = e & 31;
        xs[bc][tcc][b] = x[(size_t)(gbg + b) * TT + tcc];
    }

    const u32 hT_a    = smem_u32(hT);
    const u32 laneoff = (u32)((lane & 15) * 16);
    // byte offset of hT[buf][grp][arr]
    auto hoff = [](int buf, int grp, int arr) -> u32 {
        return (u32)((((buf * 4 + grp) * 2) + arr) * (HH * 8 * 2));
    };

    __syncthreads();

    // --- 4-phase skew: group bc delayed ~bc*160 cyc (dependent FMA chain) ---
    {
        int links = bc * 40;
        float z = biav0 + 1.0f;
        for (int i = 0; i < links; i++)
            asm volatile("fma.rn.f32 %0, %0, %1, %2;"
                         : "+f"(z) : "f"(0.9999999f), "f"(1e-30f));
        if (z == -123456.75f) xs[0][0][0] = z;   // defeat DCE, never true
    }

    int cur = 0;
    for (int t = 0; t < TT; t++) {
        const int tc = t & 31;
        if (tc == 0 && t > 0) {
            for (int e = ht; e < 8 * 32; e += 128) {
                int b = e >> 5, tcc = e & 31;
                xs[bc][tcc][b] = x[(size_t)(gbg + b) * TT + t + tcc];
            }
            bar_grp(bc);
        }

        // --- B fragments: hT[cur][bc], 4 k-slabs, hi+lo (ldmatrix.trans) ---
        u32 bhi[4][2], blo[4][2];
        const u32 bhia = hT_a + hoff(cur, bc, 0) + laneoff;
        const u32 bloa = hT_a + hoff(cur, bc, 1) + laneoff;
#pragma unroll
        for (int s = 0; s < 4; s++) {
            ldm2t(bhi[s], bhia + s * 256);
            ldm2t(blo[s], bloa + s * 256);
        }

        // 3 independent depth-4 HMMA chains (12 MMAs)
        float dA[4] = {}, dB[4] = {}, dC[4] = {};
#pragma unroll
        for (int s = 0; s < 4; s++) {
            mma16816(dA, ahi[s], bhi[s]);
            mma16816(dB, ahi[s], blo[s]);
            mma16816(dC, alo[s], bhi[s]);
        }

        // epilogue: D lane map: d0=(ig,b0) d1=(ig,b1) d2=(ig+8,b0) d3=(ig+8,b1)
        const float xv0 = xs[bc][tc][2 * tig];
        const float xv1 = xs[bc][tc][2 * tig + 1];
        const int nxt = cur ^ 1;

        float s00 = (dA[0] + dB[0]) + (dC[0] + fmaf(xv0, wihv0, biav0));
        float s01 = (dA[1] + dB[1]) + (dC[1] + fmaf(xv1, wihv0, biav0));
        float s10 = (dA[2] + dB[2]) + (dC[2] + fmaf(xv0, wihv1, biav1));
        float s11 = (dA[3] + dB[3]) + (dC[3] + fmaf(xv1, wihv1, biav1));
        float v00 = ftanh(s00), v01 = ftanh(s01);
        float v10 = ftanh(s10), v11 = ftanh(s11);

        // packed stores: hT[nxt][bc][arr][i*8 + 2tig .. +1]
        {
            __nv_bfloat16* dsthi = hT[nxt][bc][0];
            __nv_bfloat16* dstlo = hT[nxt][bc][1];
            *(u32*)&dsthi[ig * 8 + 2 * tig]       = pkbf(v00, v01);
            *(u32*)&dsthi[(ig + 8) * 8 + 2 * tig] = pkbf(v10, v11);
            float l00 = v00 - __bfloat162float(__float2bfloat16(v00));
            float l01 = v01 - __bfloat162float(__float2bfloat16(v01));
            float l10 = v10 - __bfloat162float(__float2bfloat16(v10));
            float l11 = v11 - __bfloat162float(__float2bfloat16(v11));
            *(u32*)&dstlo[ig * 8 + 2 * tig]       = pkbf(l00, l01);
            *(u32*)&dstlo[(ig + 8) * 8 + 2 * tig] = pkbf(l10, l11);
        }
        if (t == TT - 1) {
            hsfin[bc * 8 + 2 * tig][ig]         = v00;
            hsfin[bc * 8 + 2 * tig + 1][ig]     = v01;
            hsfin[bc * 8 + 2 * tig][ig + 8]     = v10;
            hsfin[bc * 8 + 2 * tig + 1][ig + 8] = v11;
        }
        bar_grp(bc);
        cur ^= 1;
    }

    __syncthreads();    // re-align groups before the head

    // --- head: out[b,c] = sum_j hT[b,j]*w_head[c,j] + b_head[c] (fp32) ---
    if (tid < NB * CC) {
        const int b = tid / CC, c = tid % CC;
        const float* hf = hsfin[b];
        float s = b_head[c];
#pragma unroll
        for (int j = 0; j < HH; j++)
            s = fmaf(hf[j], w_head[c * HH + j], s);
        out[(size_t)(gb0 + b) * CC + c] = s;
    }
}

extern "C" void kernel_launch(void* const* d_in, const int* in_sizes, int n_in,
                              void* d_out, int out_size)
{
    (void)in_sizes; (void)n_in; (void)out_size;
    const float* x      = (const float*)d_in[0];
    const float* w_ih   = (const float*)d_in[1];
    const float* b_ih   = (const float*)d_in[2];
    const float* w_hh   = (const float*)d_in[3];
    const float* b_hh   = (const float*)d_in[4];
    const float* w_head = (const float*)d_in[5];
    const float* b_head = (const float*)d_in[6];
    float* out = (float*)d_out;

    rnn_swap_kernel<<<BB / NB, NTHREADS>>>(
        x, w_ih, b_ih, w_hh, b_hh, w_head, b_head, out);
}

// round 16
// speedup vs baseline: 1.6777x; 1.1542x over previous
#include <cuda_runtime.h>
#include <cuda_fp16.h>
#include <cstdint>

// RNN: B=4096, T=1024, H=64, scalar input, C=5 head.
//   h_{t+1}[b,i] = tanh(x[b,t]*w_ih[i] + b_ih[i] + b_hh[i] + sum_j h_t[b,j]*w_hh[i,j])
//   out[b,c]     = sum_j hT[b,j]*w_head[c,j] + b_head[c]
//
// R15 = R14 (operand swap: A=W in regs, B=H n8 batch-groups, 4 anti-phased
// groups, 352us) with fp16 precision scheme:
//   - h in (-1,1) fits fp16 (11-bit mantissa): SINGLE fp16 h array
//     (error 2^-11; measured sensitivity scaling predicts ~1.5e-4 final)
//   - W = Whi(fp16) + Wlo*2048(fp16) in registers -> W error ~2^-25
//   - 2 MMA products (was 3), 4 depth-2 chains, half the ldmatrix traffic,
//     no lo-split epilogue arithmetic. HW tanh.approx kept.

#define BB 4096
#define TT 1024
#define HH 64
#define CC 5
#define NB 32
#define NTHREADS 512
#define WLO_SCALE 2048.0f
#define WLO_INV   (1.0f / 2048.0f)

typedef uint32_t u32;

__device__ __forceinline__ u32 smem_u32(const void* p) {
    u32 a;
    asm("{ .reg .u64 t; cvta.to.shared.u64 t, %1; cvt.u32.u64 %0, t; }"
        : "=r"(a) : "l"(p));
    return a;
}
__device__ __forceinline__ u32 pkh(float a, float b) {
    __half2 t = __floats2half2_rn(a, b);
    return *reinterpret_cast<u32*>(&t);
}
__device__ __forceinline__ float ftanh(float xv) {
    float y;
    asm("tanh.approx.f32 %0, %1;" : "=f"(y) : "f"(xv));
    return y;
}
__device__ __forceinline__ void ldm2t(u32* r, u32 addr) {
    asm volatile("ldmatrix.sync.aligned.m8n8.x2.trans.shared.b16 {%0,%1}, [%2];"
                 : "=r"(r[0]), "=r"(r[1]) : "r"(addr));
}
__device__ __forceinline__ void mma16816h(float* d, const u32* a, const u32* b) {
    asm volatile(
        "mma.sync.aligned.m16n8k16.row.col.f32.f16.f16.f32 "
        "{%0,%1,%2,%3}, {%4,%5,%6,%7}, {%8,%9}, {%0,%1,%2,%3};"
        : "+f"(d[0]), "+f"(d[1]), "+f"(d[2]), "+f"(d[3])
        : "r"(a[0]), "r"(a[1]), "r"(a[2]), "r"(a[3]), "r"(b[0]), "r"(b[1]));
}
__device__ __forceinline__ void bar_grp(int id) {
    asm volatile("bar.sync %0, 128;" :: "r"(1 + id) : "memory");
}

extern "C" __global__ void __launch_bounds__(NTHREADS, 1)
rnn_fp16_kernel(const float* __restrict__ x,
                const float* __restrict__ w_ih,
                const float* __restrict__ b_ih,
                const float* __restrict__ w_hh,
                const float* __restrict__ b_hh,
                const float* __restrict__ w_head,
                const float* __restrict__ b_head,
                float* __restrict__ out)
{
    // hT[buf][group][j(64) * b(8)] fp16, 16B rows -> 8 KB total
    __shared__ __align__(16) __half hT[2][4][HH * 8];
    __shared__ float xs[4][32][8];            // 4 KB  [group][tc][b]
    __shared__ float hsfin[NB][HH];           // 8 KB

    const int tid  = threadIdx.x;
    const int lane = tid & 31;
    const int wrp  = tid >> 5;
    const int bc   = wrp >> 2;          // batch group 0..3 (8 batches)
    const int ir   = wrp & 3;           // i-tile 0..3 (16 i's)
    const int tig  = lane & 3;
    const int gid  = lane >> 2;
    const int ht   = tid & 127;         // thread id within group
    const int gb0  = blockIdx.x * NB;
    const int gbg  = gb0 + bc * 8;      // group's global batch base

    // --- A fragments: W rows (loop-invariant), fp16 hi + scaled-lo ---
    // lane (gid,tig): rows ig, ig+8; k = slab*16 + {2tig,2tig+1, +8,+9}
    const int ig = ir * 16 + gid;
    u32 ahi[4][4], alo[4][4];
#pragma unroll
    for (int s = 0; s < 4; s++) {
        const float* w0 = w_hh + (size_t)ig * HH + s * 16;
        const float* w1 = w_hh + (size_t)(ig + 8) * HH + s * 16;
        float e[2][4] = {
            { w0[2*tig], w0[2*tig + 1], w0[2*tig + 8], w0[2*tig + 9] },
            { w1[2*tig], w1[2*tig + 1], w1[2*tig + 8], w1[2*tig + 9] } };
        float l[2][4];
#pragma unroll
        for (int r = 0; r < 2; r++)
#pragma unroll
            for (int q = 0; q < 4; q++)
                l[r][q] = (e[r][q] - __half2float(__float2half_rn(e[r][q]))) * WLO_SCALE;
        ahi[s][0] = pkh(e[0][0], e[0][1]);
        ahi[s][1] = pkh(e[1][0], e[1][1]);
        ahi[s][2] = pkh(e[0][2], e[0][3]);
        ahi[s][3] = pkh(e[1][2], e[1][3]);
        alo[s][0] = pkh(l[0][0], l[0][1]);
        alo[s][1] = pkh(l[1][0], l[1][1]);
        alo[s][2] = pkh(l[0][2], l[0][3]);
        alo[s][3] = pkh(l[1][2], l[1][3]);
    }

    // --- epilogue constants: this lane's two i rows ---
    const float wihv0 = w_ih[ig],     wihv1 = w_ih[ig + 8];
    const float biav0 = b_ih[ig] + b_hh[ig];
    const float biav1 = b_ih[ig + 8] + b_hh[ig + 8];

    // --- zero h buffer 0 ---
    for (int e = tid; e < 4 * HH * 8 / 2; e += NTHREADS)
        ((u32*)hT[0])[e] = 0u;

    // --- stage x chunk 0 (per group) ---
    for (int e = ht; e < 8 * 32; e += 128) {
        int b = e >> 5, tcc = e & 31;
        xs[bc][tcc][b] = x[(size_t)(gbg + b) * TT + tcc];
    }

    const u32 hT_a    = smem_u32(hT);
    const u32 laneoff = (u32)((lane & 15) * 16);
    // byte offset of hT[buf][grp]
    auto hoff = [](int buf, int grp) -> u32 {
        return (u32)((buf * 4 + grp) * (HH * 8 * 2));
    };

    __syncthreads();

    // --- 4-phase skew: group bc delayed ~bc*160 cyc (dependent FMA chain) ---
    {
        int links = bc * 40;
        float z = biav0 + 1.0f;
        for (int i = 0; i < links; i++)
            asm volatile("fma.rn.f32 %0, %0, %1, %2;"
                         : "+f"(z) : "f"(0.9999999f), "f"(1e-30f));
        if (z == -123456.75f) xs[0][0][0] = z;   // defeat DCE, never true
    }

    int cur = 0;
    for (int t = 0; t < TT; t++) {
        const int tc = t & 31;
        if (tc == 0 && t > 0) {
            for (int e = ht; e < 8 * 32; e += 128) {
                int b = e >> 5, tcc = e & 31;
                xs[bc][tcc][b] = x[(size_t)(gbg + b) * TT + t + tcc];
            }
            bar_grp(bc);
        }

        // --- B fragments: hT[cur][bc], 4 k-slabs (ldmatrix.trans) ---
        u32 bh[4][2];
        const u32 ba = hT_a + hoff(cur, bc) + laneoff;
#pragma unroll
        for (int s = 0; s < 4; s++) ldm2t(bh[s], ba + s * 256);

        // 4 independent depth-2 HMMA chains (8 MMAs)
        float dA0[4] = {}, dA1[4] = {}, dB0[4] = {}, dB1[4] = {};
        mma16816h(dA0, ahi[0], bh[0]);
        mma16816h(dB0, alo[0], bh[0]);
        mma16816h(dA1, ahi[1], bh[1]);
        mma16816h(dB1, alo[1], bh[1]);
        mma16816h(dA0, ahi[2], bh[2]);
        mma16816h(dB0, alo[2], bh[2]);
        mma16816h(dA1, ahi[3], bh[3]);
        mma16816h(dB1, alo[3], bh[3]);

        // epilogue: D lane map: d0=(ig,b0) d1=(ig,b1) d2=(ig+8,b0) d3=(ig+8,b1)
        const float xv0 = xs[bc][tc][2 * tig];
        const float xv1 = xs[bc][tc][2 * tig + 1];
        const int nxt = cur ^ 1;

        float s00 = fmaf(dB0[0] + dB1[0], WLO_INV, dA0[0] + dA1[0]) + fmaf(xv0, wihv0, biav0);
        float s01 = fmaf(dB0[1] + dB1[1], WLO_INV, dA0[1] + dA1[1]) + fmaf(xv1, wihv0, biav0);
        float s10 = fmaf(dB0[2] + dB1[2], WLO_INV, dA0[2] + dA1[2]) + fmaf(xv0, wihv1, biav1);
        float s11 = fmaf(dB0[3] + dB1[3], WLO_INV, dA0[3] + dA1[3]) + fmaf(xv1, wihv1, biav1);
        float v00 = ftanh(s00), v01 = ftanh(s01);
        float v10 = ftanh(s10), v11 = ftanh(s11);

        // packed stores: hT[nxt][bc][i*8 + 2tig .. +1]
        {
            __half* dsth = hT[nxt][bc];
            *(u32*)&dsth[ig * 8 + 2 * tig]       = pkh(v00, v01);
            *(u32*)&dsth[(ig + 8) * 8 + 2 * tig] = pkh(v10, v11);
        }
        if (t == TT - 1) {
            hsfin[bc * 8 + 2 * tig][ig]         = v00;
            hsfin[bc * 8 + 2 * tig + 1][ig]     = v01;
            hsfin[bc * 8 + 2 * tig][ig + 8]     = v10;
            hsfin[bc * 8 + 2 * tig + 1][ig + 8] = v11;
        }
        bar_grp(bc);
        cur ^= 1;
    }

    __syncthreads();    // re-align groups before the head

    // --- head: out[b,c] = sum_j hT[b,j]*w_head[c,j] + b_head[c] (fp32) ---
    if (tid < NB * CC) {
        const int b = tid / CC, c = tid % CC;
        const float* hf = hsfin[b];
        float s = b_head[c];
#pragma unroll
        for (int j = 0; j < HH; j++)
            s = fmaf(hf[j], w_head[c * HH + j], s);
        out[(size_t)(gb0 + b) * CC + c] = s;
    }
}

extern "C" void kernel_launch(void* const* d_in, const int* in_sizes, int n_in,
                              void* d_out, int out_size)
{
    (void)in_sizes; (void)n_in; (void)out_size;
    const float* x      = (const float*)d_in[0];
    const float* w_ih   = (const float*)d_in[1];
    const float* b_ih   = (const float*)d_in[2];
    const float* w_hh   = (const float*)d_in[3];
    const float* b_hh   = (const float*)d_in[4];
    const float* w_head = (const float*)d_in[5];
    const float* b_head = (const float*)d_in[6];
    float* out = (float*)d_out;

    rnn_fp16_kernel<<<BB / NB, NTHREADS>>>(
        x, w_ih, b_ih, w_hh, b_hh, w_head, b_head, out);
}

// round 17
// speedup vs baseline: 2.0151x; 1.2011x over previous
#include <cuda_runtime.h>
#include <cuda_fp16.h>
#include <cstdint>

// RNN: B=4096, T=1024, H=64, scalar input, C=5 head.
//   h_{t+1}[b,i] = tanh(x[b,t]*w_ih[i] + b_ih[i] + b_hh[i] + sum_j h_t[b,j]*w_hh[i,j])
//   out[b,c]     = sum_j hT[b,j]*w_head[c,j] + b_head[c]
//
// R16 = R15 (A=W regs fp16 hi+lo, B=H n8 groups, 4 anti-phased groups,
// 305us) + packed epilogue: cvt.rn.f16x2.f32 pairs the two fp32
// pre-activations, tanh.approx.f16x2 produces both fp16 h values in ONE
// MUFU op, stored directly. MUFU tail halved. Periodic re-skew at each
// 32-step x-stage boundary keeps the 4-phase group rotation alive.

#define BB 4096
#define TT 1024
#define HH 64
#define CC 5
#define NB 32
#define NTHREADS 512
#define WLO_SCALE 2048.0f
#define WLO_INV   (1.0f / 2048.0f)

typedef uint32_t u32;

__device__ __forceinline__ u32 smem_u32(const void* p) {
    u32 a;
    asm("{ .reg .u64 t; cvta.to.shared.u64 t, %1; cvt.u32.u64 %0, t; }"
        : "=r"(a) : "l"(p));
    return a;
}
__device__ __forceinline__ u32 pkh(float a, float b) {
    __half2 t = __floats2half2_rn(a, b);
    return *reinterpret_cast<u32*>(&t);
}
// pack {lo=a, hi=b} then tanh both halves in one MUFU op
__device__ __forceinline__ u32 tanh2(float a, float b) {
    u32 p, v;
    asm("cvt.rn.f16x2.f32 %0, %1, %2;" : "=r"(p) : "f"(b), "f"(a));
    asm("tanh.approx.f16x2 %0, %1;" : "=r"(v) : "r"(p));
    return v;
}
__device__ __forceinline__ void ldm2t(u32* r, u32 addr) {
    asm volatile("ldmatrix.sync.aligned.m8n8.x2.trans.shared.b16 {%0,%1}, [%2];"
                 : "=r"(r[0]), "=r"(r[1]) : "r"(addr));
}
__device__ __forceinline__ void mma16816h(float* d, const u32* a, const u32* b) {
    asm volatile(
        "mma.sync.aligned.m16n8k16.row.col.f32.f16.f16.f32 "
        "{%0,%1,%2,%3}, {%4,%5,%6,%7}, {%8,%9}, {%0,%1,%2,%3};"
        : "+f"(d[0]), "+f"(d[1]), "+f"(d[2]), "+f"(d[3])
        : "r"(a[0]), "r"(a[1]), "r"(a[2]), "r"(a[3]), "r"(b[0]), "r"(b[1]));
}
__device__ __forceinline__ void bar_grp(int id) {
    asm volatile("bar.sync %0, 128;" :: "r"(1 + id) : "memory");
}
__device__ __forceinline__ void skew_delay(int links, float seed, float* sink) {
    float z = seed + 1.0f;
    for (int i = 0; i < links; i++)
        asm volatile("fma.rn.f32 %0, %0, %1, %2;"
                     : "+f"(z) : "f"(0.9999999f), "f"(1e-30f));
    if (z == -123456.75f) *sink = z;   // defeat DCE, never true
}

extern "C" __global__ void __launch_bounds__(NTHREADS, 1)
rnn_f16x2_kernel(const float* __restrict__ x,
                 const float* __restrict__ w_ih,
                 const float* __restrict__ b_ih,
                 const float* __restrict__ w_hh,
                 const float* __restrict__ b_hh,
                 const float* __restrict__ w_head,
                 const float* __restrict__ b_head,
                 float* __restrict__ out)
{
    // hT[buf][group][j(64) * b(8)] fp16, 16B rows -> 8 KB total
    __shared__ __align__(16) __half hT[2][4][HH * 8];
    __shared__ float xs[4][32][8];            // 4 KB  [group][tc][b]
    __shared__ float hsfin[NB][HH];           // 8 KB

    const int tid  = threadIdx.x;
    const int lane = tid & 31;
    const int wrp  = tid >> 5;
    const int bc   = wrp >> 2;          // batch group 0..3 (8 batches)
    const int ir   = wrp & 3;           // i-tile 0..3 (16 i's)
    const int tig  = lane & 3;
    const int gid  = lane >> 2;
    const int ht   = tid & 127;         // thread id within group
    const int gb0  = blockIdx.x * NB;
    const int gbg  = gb0 + bc * 8;      // group's global batch base

    // --- A fragments: W rows (loop-invariant), fp16 hi + scaled-lo ---
    const int ig = ir * 16 + gid;
    u32 ahi[4][4], alo[4][4];
#pragma unroll
    for (int s = 0; s < 4; s++) {
        const float* w0 = w_hh + (size_t)ig * HH + s * 16;
        const float* w1 = w_hh + (size_t)(ig + 8) * HH + s * 16;
        float e[2][4] = {
            { w0[2*tig], w0[2*tig + 1], w0[2*tig + 8], w0[2*tig + 9] },
            { w1[2*tig], w1[2*tig + 1], w1[2*tig + 8], w1[2*tig + 9] } };
        float l[2][4];
#pragma unroll
        for (int r = 0; r < 2; r++)
#pragma unroll
            for (int q = 0; q < 4; q++)
                l[r][q] = (e[r][q] - __half2float(__float2half_rn(e[r][q]))) * WLO_SCALE;
        ahi[s][0] = pkh(e[0][0], e[0][1]);
        ahi[s][1] = pkh(e[1][0], e[1][1]);
        ahi[s][2] = pkh(e[0][2], e[0][3]);
        ahi[s][3] = pkh(e[1][2], e[1][3]);
        alo[s][0] = pkh(l[0][0], l[0][1]);
        alo[s][1] = pkh(l[1][0], l[1][1]);
        alo[s][2] = pkh(l[0][2], l[0][3]);
        alo[s][3] = pkh(l[1][2], l[1][3]);
    }

    // --- epilogue constants: this lane's two i rows ---
    const float wihv0 = w_ih[ig],     wihv1 = w_ih[ig + 8];
    const float biav0 = b_ih[ig] + b_hh[ig];
    const float biav1 = b_ih[ig + 8] + b_hh[ig + 8];

    // --- zero h buffer 0 ---
    for (int e = tid; e < 4 * HH * 8 / 2; e += NTHREADS)
        ((u32*)hT[0])[e] = 0u;

    // --- stage x chunk 0 (per group) ---
    for (int e = ht; e < 8 * 32; e += 128) {
        int b = e >> 5, tcc = e & 31;
        xs[bc][tcc][b] = x[(size_t)(gbg + b) * TT + tcc];
    }

    const u32 hT_a    = smem_u32(hT);
    const u32 laneoff = (u32)((lane & 15) * 16);
    auto hoff = [](int buf, int grp) -> u32 {
        return (u32)((buf * 4 + grp) * (HH * 8 * 2));
    };

    __syncthreads();

    // --- initial 4-phase skew: group bc delayed ~bc*160 cyc ---
    skew_delay(bc * 40, biav0, &xs[0][0][0]);

    int cur = 0;
    for (int t = 0; t < TT; t++) {
        const int tc = t & 31;
        if (tc == 0 && t > 0) {
            for (int e = ht; e < 8 * 32; e += 128) {
                int b = e >> 5, tcc = e & 31;
                xs[bc][tcc][b] = x[(size_t)(gbg + b) * TT + t + tcc];
            }
            bar_grp(bc);
            // periodic re-skew: keep the 4-phase rotation from decaying
            skew_delay(bc * 24, biav0, &xs[0][0][0]);
        }

        // base terms (independent of MMA accumulators -> off critical path)
        const float xv0 = xs[bc][tc][2 * tig];
        const float xv1 = xs[bc][tc][2 * tig + 1];
        const float base00 = fmaf(xv0, wihv0, biav0);
        const float base01 = fmaf(xv1, wihv0, biav0);
        const float base10 = fmaf(xv0, wihv1, biav1);
        const float base11 = fmaf(xv1, wihv1, biav1);

        // --- B fragments: hT[cur][bc], 4 k-slabs (ldmatrix.trans) ---
        u32 bh[4][2];
        const u32 ba = hT_a + hoff(cur, bc) + laneoff;
#pragma unroll
        for (int s = 0; s < 4; s++) ldm2t(bh[s], ba + s * 256);

        // 4 independent depth-2 HMMA chains (8 MMAs)
        float dA0[4] = {}, dA1[4] = {}, dB0[4] = {}, dB1[4] = {};
        mma16816h(dA0, ahi[0], bh[0]);
        mma16816h(dB0, alo[0], bh[0]);
        mma16816h(dA1, ahi[1], bh[1]);
        mma16816h(dB1, alo[1], bh[1]);
        mma16816h(dA0, ahi[2], bh[2]);
        mma16816h(dB0, alo[2], bh[2]);
        mma16816h(dA1, ahi[3], bh[3]);
        mma16816h(dB1, alo[3], bh[3]);

        // epilogue: combine, packed f16x2 tanh, direct store
        const int nxt = cur ^ 1;
        float s00 = fmaf(dB0[0] + dB1[0], WLO_INV, dA0[0] + dA1[0]) + base00;
        float s01 = fmaf(dB0[1] + dB1[1], WLO_INV, dA0[1] + dA1[1]) + base01;
        float s10 = fmaf(dB0[2] + dB1[2], WLO_INV, dA0[2] + dA1[2]) + base10;
        float s11 = fmaf(dB0[3] + dB1[3], WLO_INV, dA0[3] + dA1[3]) + base11;
        u32 v0 = tanh2(s00, s01);   // {lo: tanh(s00), hi: tanh(s01)}
        u32 v1 = tanh2(s10, s11);

        {
            __half* dsth = hT[nxt][bc];
            *(u32*)&dsth[ig * 8 + 2 * tig]       = v0;
            *(u32*)&dsth[(ig + 8) * 8 + 2 * tig] = v1;
        }
        if (t == TT - 1) {
            float2 f0 = __half22float2(*reinterpret_cast<__half2*>(&v0));
            float2 f1 = __half22float2(*reinterpret_cast<__half2*>(&v1));
            hsfin[bc * 8 + 2 * tig][ig]         = f0.x;
            hsfin[bc * 8 + 2 * tig + 1][ig]     = f0.y;
            hsfin[bc * 8 + 2 * tig][ig + 8]     = f1.x;
            hsfin[bc * 8 + 2 * tig + 1][ig + 8] = f1.y;
        }
        bar_grp(bc);
        cur ^= 1;
    }

    __syncthreads();    // re-align groups before the head

    // --- head: out[b,c] = sum_j hT[b,j]*w_head[c,j] + b_head[c] (fp32) ---
    if (tid < NB * CC) {
        const int b = tid / CC, c = tid % CC;
        const float* hf = hsfin[b];
        float s = b_head[c];
#pragma unroll
        for (int j = 0; j < HH; j++)
            s = fmaf(hf[j], w_head[c * HH + j], s);
        out[(size_t)(gb0 + b) * CC + c] = s;
    }
}

extern "C" void kernel_launch(void* const* d_in, const int* in_sizes, int n_in,
                              void* d_out, int out_size)
{
    (void)in_sizes; (void)n_in; (void)out_size;
    const float* x      = (const float*)d_in[0];
    const float* w_ih   = (const float*)d_in[1];
    const float* b_ih   = (const float*)d_in[2];
    const float* w_hh   = (const float*)d_in[3];
    const float* b_hh   = (const float*)d_in[4];
    const float* w_head = (const float*)d_in[5];
    const float* b_head = (const float*)d_in[6];
    float* out = (float*)d_out;

    rnn_f16x2_kernel<<<BB / NB, NTHREADS>>>(
        x, w_ih, b_ih, w_hh, b_hh, w_head, b_head, out);
}